// round 1
// baseline (speedup 1.0000x reference)
#include <cuda_runtime.h>
#include <cstdint>

#define BATCH 4
#define CCH   32
#define IMG   256
#define GRID_ 32          // hs = ws
#define TDIM  33          // 264/8 output tiles per dim
#define TT    (TDIM*TDIM) // 1089
#define KDIM  TT          // 1089
#define KPAD  1104        // 69*16
#define MPAD  1152        // 9*128
#define NCOLS (33*64)     // 2112  (33 channels x 8x8 offsets)

#define OFF_MR  (BATCH*CCH*IMG*IMG)        // 8388608
#define OFF_RC  (OFF_MR + BATCH*IMG*IMG)   // 8650752

// ---------------- scratch (device globals; no runtime allocation) -------------
__device__ float g_Fhat[BATCH * KPAD * NCOLS]; // [b][k][n]  ~37.3 MB
__device__ float g_At  [BATCH * KPAD * MPAD];  // [b][k][t]  ~20.3 MB (A transposed)
__device__ int   g_ids [BATCH * GRID_ * GRID_];

// ---------------- helpers ------------------------------------------------------
__device__ __forceinline__ unsigned long long pack2(float x, float y) {
    unsigned long long r;
    asm("mov.b64 %0, {%1, %2};" : "=l"(r) : "f"(x), "f"(y));
    return r;
}
__device__ __forceinline__ void ffma2(unsigned long long& d,
                                      unsigned long long a, unsigned long long b) {
    asm("fma.rn.f32x2 %0, %1, %2, %0;" : "+l"(d) : "l"(a), "l"(b));
}
__device__ __forceinline__ void cp_async16(uint32_t saddr, const void* g) {
    asm volatile("cp.async.cg.shared.global [%0], [%1], 16;\n" :: "r"(saddr), "l"(g));
}

// ---------------- K1: build Fhat[m, (c,dy,dx)] = F[c, 8my+dy, 8mx+dx] ----------
__global__ void prep_fhat(const float* __restrict__ bimg, const float* __restrict__ mask) {
    int idx = blockIdx.x * blockDim.x + threadIdx.x;
    const int per_b = KPAD * NCOLS;
    if (idx >= BATCH * per_b) return;
    int b = idx / per_b;
    int r = idx - b * per_b;
    int k = r / NCOLS;
    int n = r - k * NCOLS;
    float val = 0.f;
    if (k < KDIM) {
        int my = k / TDIM, mx = k - my * TDIM;
        int c  = n >> 6;
        int dy = (n >> 3) & 7;
        int dx = n & 7;
        int u = my * 8 + dy - 4; u = max(0, min(IMG - 1, u));  // replicate pad
        int v = mx * 8 + dx - 4; v = max(0, min(IMG - 1, v));
        float m = mask[(b * IMG + u) * IMG + v];
        if (c < CCH) val = bimg[((b * CCH + c) * IMG + u) * IMG + v] * (1.f - m);
        else         val = m;
    }
    g_Fhat[idx] = val;
}

// ---------------- K2: build At[k][t] = sum_q cos[(my-qy,mx-qx),(Ty-qy,Tx-qx)] ---
__global__ void prep_at(const float* __restrict__ cosd) {
    int idx = blockIdx.x * blockDim.x + threadIdx.x;
    const int per_b = KPAD * MPAD;
    if (idx >= BATCH * per_b) return;
    int b = idx / per_b;
    int r = idx - b * per_b;
    int k = r / MPAD;
    int t = r - k * MPAD;
    float s = 0.f;
    if (k < KDIM && t < TT) {
        int my = k / TDIM, mx = k - my * TDIM;
        int Ty = t / TDIM, Tx = t - Ty * TDIM;
        const float* cb = cosd + (size_t)b * GRID_ * GRID_ * GRID_ * GRID_;
        #pragma unroll
        for (int qy = 0; qy < 2; qy++) {
            int ny = my - qy, gy = Ty - qy;
            if ((unsigned)ny < GRID_ && (unsigned)gy < GRID_) {
                #pragma unroll
                for (int qx = 0; qx < 2; qx++) {
                    int nx = mx - qx, gx = Tx - qx;
                    if ((unsigned)nx < GRID_ && (unsigned)gx < GRID_)
                        s += cb[((ny * GRID_ + nx) * GRID_ + gy) * GRID_ + gx];
                }
            }
        }
    }
    g_At[idx] = s;
}

// ---------------- K3: GEMM  D[t,n] = sum_k At[k][t] * Fhat[k][n] ----------------
// Epilogue writes output (c<32) and mask_recon (c==32, /wm) directly with crop.
#define BM 128
#define BN 64
#define BK 16

__global__ __launch_bounds__(256, 2) void gemm_kernel(float* __restrict__ out) {
    __shared__ float As[2][BK][BM];
    __shared__ float Bs[2][BK][BN];

    const int b   = blockIdx.z;
    const int t0  = blockIdx.x * BM;
    const int n0  = blockIdx.y * BN;
    const int tid = threadIdx.x;
    const int ty  = tid >> 4;   // 0..15 (t rows, 8 each)
    const int tx  = tid & 15;   // 0..15 (n cols, 4 each)

    const float* Abase = g_At   + (size_t)b * KPAD * MPAD;
    const float* Bbase = g_Fhat + (size_t)b * KPAD * NCOLS;

    unsigned long long acc[4][4];
    #pragma unroll
    for (int p = 0; p < 4; p++)
        #pragma unroll
        for (int j = 0; j < 4; j++) acc[p][j] = 0ull;

    auto loadTile = [&](int kt, int st) {
        int k0 = kt * BK;
        #pragma unroll
        for (int q = 0; q < 2; q++) {
            int i   = tid + q * 256;
            int row = i >> 5;
            int col = (i & 31) * 4;
            uint32_t sa = (uint32_t)__cvta_generic_to_shared(&As[st][row][col]);
            cp_async16(sa, Abase + (k0 + row) * MPAD + t0 + col);
        }
        {
            int row = tid >> 4;
            int col = (tid & 15) * 4;
            uint32_t sb = (uint32_t)__cvta_generic_to_shared(&Bs[st][row][col]);
            cp_async16(sb, Bbase + (k0 + row) * NCOLS + n0 + col);
        }
        asm volatile("cp.async.commit_group;\n");
    };

    const int NK = KPAD / BK;  // 69
    loadTile(0, 0);

    for (int kt = 0; kt < NK; kt++) {
        if (kt + 1 < NK) {
            loadTile(kt + 1, (kt + 1) & 1);
            asm volatile("cp.async.wait_group 1;\n");
        } else {
            asm volatile("cp.async.wait_group 0;\n");
        }
        __syncthreads();

        const int s = kt & 1;
        #pragma unroll
        for (int kk = 0; kk < BK; kk++) {
            ulonglong2 a01 = *reinterpret_cast<const ulonglong2*>(&As[s][kk][ty * 8]);
            ulonglong2 a23 = *reinterpret_cast<const ulonglong2*>(&As[s][kk][ty * 8 + 4]);
            float4 bv = *reinterpret_cast<const float4*>(&Bs[s][kk][tx * 4]);
            unsigned long long ap[4] = { a01.x, a01.y, a23.x, a23.y };
            unsigned long long bp[4] = { pack2(bv.x, bv.x), pack2(bv.y, bv.y),
                                         pack2(bv.z, bv.z), pack2(bv.w, bv.w) };
            #pragma unroll
            for (int p = 0; p < 4; p++)
                #pragma unroll
                for (int j = 0; j < 4; j++)
                    ffma2(acc[p][j], ap[p], bp[j]);
        }
        __syncthreads();
    }

    // epilogue: D[t, n] -> out_padded[c, 8Ty+dy, 8Tx+dx], crop [4,260)
    #pragma unroll
    for (int p = 0; p < 4; p++) {
        #pragma unroll
        for (int lane = 0; lane < 2; lane++) {
            int t = t0 + ty * 8 + p * 2 + lane;
            if (t >= TT) continue;
            int Ty = t / TDIM, Tx = t - Ty * TDIM;
            int cnty = (Ty >= 1) + (Ty <= 31);
            int cntx = (Tx >= 1) + (Tx <= 31);
            #pragma unroll
            for (int j = 0; j < 4; j++) {
                int n  = n0 + tx * 4 + j;
                int c  = n >> 6;
                int dy = (n >> 3) & 7;
                int dx = n & 7;
                int py = Ty * 8 + dy, px = Tx * 8 + dx;
                if (py < 4 || py >= 260 || px < 4 || px >= 260) continue;
                int y = py - 4, x = px - 4;
                unsigned long long v = acc[p][j];
                uint32_t bits = lane ? (uint32_t)(v >> 32) : (uint32_t)v;
                float f = __uint_as_float(bits);
                if (c < CCH) {
                    out[((b * CCH + c) * IMG + y) * IMG + x] = f;
                } else {
                    out[OFF_MR + (b * IMG + y) * IMG + x] = f / (float)(cnty * cntx);
                }
            }
        }
    }
}

// ---------------- K4a: argmax over n for each (b, g) ---------------------------
__global__ void argmax_kernel(const float* __restrict__ cosd) {
    int b  = blockIdx.y;
    int g  = blockIdx.x * 32 + threadIdx.x;
    int ty = threadIdx.y;
    const float* cb = cosd + (size_t)b * 1024 * 1024;
    float best = -3.4e38f;
    int   bi   = 1024;
    for (int n = ty; n < 1024; n += 8) {
        float v = cb[n * 1024 + g];
        if (v > best) { best = v; bi = n; }
    }
    __shared__ float sv[8][32];
    __shared__ int   si[8][32];
    sv[ty][threadIdx.x] = best;
    si[ty][threadIdx.x] = bi;
    __syncthreads();
    if (ty == 0) {
        #pragma unroll
        for (int r = 1; r < 8; r++) {
            float v = sv[r][threadIdx.x];
            int   i2 = si[r][threadIdx.x];
            if (v > best || (v == best && i2 < bi)) { best = v; bi = i2; }
        }
        g_ids[b * 1024 + g] = bi;
    }
}

// ---------------- K4b: recon via argmax gather ---------------------------------
__global__ void recon_kernel(const float* __restrict__ aux, float* __restrict__ out) {
    int idx = blockIdx.x * blockDim.x + threadIdx.x;
    if (idx >= BATCH * 3 * IMG * IMG) return;
    int x = idx & 255;
    int y = (idx >> 8) & 255;
    int bc = idx >> 16;              // b*3 + c
    int b  = bc / 3;
    int py = y + 4, px = x + 4;
    int Ty = py >> 3, dy = py & 7;
    int Tx = px >> 3, dx = px & 7;
    const int*   ids = g_ids + b * 1024;
    const float* ab  = aux + (size_t)bc * IMG * IMG;
    float s = 0.f;
    #pragma unroll
    for (int qy = 0; qy < 2; qy++) {
        int gy = Ty - qy;
        if ((unsigned)gy >= GRID_) continue;
        int i = dy + 8 * qy;
        #pragma unroll
        for (int qx = 0; qx < 2; qx++) {
            int gx = Tx - qx;
            if ((unsigned)gx >= GRID_) continue;
            int j  = dx + 8 * qx;
            int id = ids[gy * 32 + gx];
            int u = (id >> 5) * 8 + i - 4; u = max(0, min(255, u));
            int v = (id & 31) * 8 + j - 4; v = max(0, min(255, v));
            s += ab[u * IMG + v];
        }
    }
    int cnty = (Ty >= 1) + (Ty <= 31);
    int cntx = (Tx >= 1) + (Tx <= 31);
    out[OFF_RC + idx] = s / (float)(cnty * cntx);
}

// ---------------- launch -------------------------------------------------------
extern "C" void kernel_launch(void* const* d_in, const int* in_sizes, int n_in,
                              void* d_out, int out_size) {
    const float* cosd = (const float*)d_in[0];
    const float* bimg = (const float*)d_in[1];
    const float* mask = (const float*)d_in[2];
    const float* aux  = (const float*)d_in[3];
    float* out = (float*)d_out;

    int nf = BATCH * KPAD * NCOLS;
    prep_fhat<<<(nf + 255) / 256, 256>>>(bimg, mask);

    int na = BATCH * KPAD * MPAD;
    prep_at<<<(na + 255) / 256, 256>>>(cosd);

    argmax_kernel<<<dim3(32, BATCH), dim3(32, 8)>>>(cosd);

    gemm_kernel<<<dim3(MPAD / BM, NCOLS / BN, BATCH), 256>>>(out);

    int nr = BATCH * 3 * IMG * IMG;
    recon_kernel<<<(nr + 255) / 256, 256>>>(aux, out);
}

// round 3
// speedup vs baseline: 1.3235x; 1.3235x over previous
#include <cuda_runtime.h>
#include <cuda_bf16.h>
#include <cstdint>

#define BATCH 4
#define CCH   32
#define IMG   256
#define GRID_ 32
#define TDIM  33
#define TT    (TDIM*TDIM)   // 1089
#define KSEG  1104          // one split segment (1089 padded to mult of 16)
#define KP    3328          // 3*1104 = 3312, padded to mult of 64
#define MPAD  1152          // 9 * 128
#define NREAL 2112          // 33 * 64
#define NPAD  2176          // 17 * 128

#define OFF_MR  (BATCH*CCH*IMG*IMG)        // 8388608
#define OFF_RC  (OFF_MR + BATCH*IMG*IMG)   // 8650752

// ---------------- scratch ------------------------------------------------------
__device__ __nv_bfloat16 g_A[(size_t)BATCH * MPAD * KP];  // ~30.7 MB [b][t][k']
__device__ __nv_bfloat16 g_B[(size_t)BATCH * NPAD * KP];  // ~58.0 MB [b][n][k']
__device__ int           g_ids[BATCH * GRID_ * GRID_];

// ---------------- helpers ------------------------------------------------------
__device__ __forceinline__ void cp_async16(uint32_t saddr, const void* g) {
    asm volatile("cp.async.cg.shared.global [%0], [%1], 16;\n" :: "r"(saddr), "l"(g));
}

// ---------------- K1: A' = [Ah | Ah | Al] --------------------------------------
__global__ void prep_A(const float* __restrict__ cosd) {
    int idx = blockIdx.x * blockDim.x + threadIdx.x;
    const int per_b = MPAD * KSEG;
    if (idx >= BATCH * per_b) return;
    int b  = idx / per_b;
    int r  = idx - b * per_b;
    int t  = r / KSEG;
    int kk = r - t * KSEG;
    float s = 0.f;
    if (t < TT && kk < TT) {
        int my = kk / TDIM, mx = kk - my * TDIM;
        int Ty = t / TDIM,  Tx = t - Ty * TDIM;
        const float* cb = cosd + (size_t)b * 1024 * 1024;
        #pragma unroll
        for (int qy = 0; qy < 2; qy++) {
            int ny = my - qy, gy = Ty - qy;
            if ((unsigned)ny < GRID_ && (unsigned)gy < GRID_) {
                #pragma unroll
                for (int qx = 0; qx < 2; qx++) {
                    int nx = mx - qx, gx = Tx - qx;
                    if ((unsigned)nx < GRID_ && (unsigned)gx < GRID_)
                        s += cb[((ny * GRID_ + nx) * GRID_ + gy) * GRID_ + gx];
                }
            }
        }
    }
    __nv_bfloat16 hi = __float2bfloat16(s);
    __nv_bfloat16 lo = __float2bfloat16(s - __bfloat162float(hi));
    __nv_bfloat16* row = g_A + ((size_t)b * MPAD + t) * KP;
    row[kk]            = hi;
    row[kk + KSEG]     = hi;
    row[kk + 2 * KSEG] = lo;
}

// ---------------- K2: B' = [Bh | Bl | Bh] --------------------------------------
__global__ void prep_B(const float* __restrict__ bimg, const float* __restrict__ mask) {
    int idx = blockIdx.x * blockDim.x + threadIdx.x;
    const int per_b = NPAD * KSEG;
    if (idx >= BATCH * per_b) return;
    int b  = idx / per_b;
    int r  = idx - b * per_b;
    int n  = r / KSEG;
    int kk = r - n * KSEG;
    float val = 0.f;
    if (kk < TT && n < NREAL) {
        int my = kk / TDIM, mx = kk - my * TDIM;
        int c  = n >> 6;
        int dy = (n >> 3) & 7;
        int dx = n & 7;
        int u = my * 8 + dy - 4; u = max(0, min(IMG - 1, u));
        int v = mx * 8 + dx - 4; v = max(0, min(IMG - 1, v));
        float m = mask[(b * IMG + u) * IMG + v];
        if (c < CCH) val = bimg[((b * CCH + c) * IMG + u) * IMG + v] * (1.f - m);
        else         val = m;
    }
    __nv_bfloat16 hi = __float2bfloat16(val);
    __nv_bfloat16 lo = __float2bfloat16(val - __bfloat162float(hi));
    __nv_bfloat16* row = g_B + ((size_t)b * NPAD + n) * KP;
    row[kk]            = hi;
    row[kk + KSEG]     = lo;
    row[kk + 2 * KSEG] = hi;
}

// ---------------- K3: zero-pad k' in [3312, 3328) ------------------------------
__global__ void pad_K() {
    int idx = blockIdx.x * blockDim.x + threadIdx.x;
    const int nA = BATCH * MPAD * 16;
    const int nB = BATCH * NPAD * 16;
    if (idx < nA) {
        int b = idx / (MPAD * 16); int r = idx - b * MPAD * 16;
        g_A[((size_t)b * MPAD + r / 16) * KP + 3312 + (r & 15)] = __float2bfloat16(0.f);
    } else if (idx < nA + nB) {
        idx -= nA;
        int b = idx / (NPAD * 16); int r = idx - b * NPAD * 16;
        g_B[((size_t)b * NPAD + r / 16) * KP + 3312 + (r & 15)] = __float2bfloat16(0.f);
    }
}

// ---------------- K4: HMMA GEMM 128x128x32, warp 64x32, m16n8k16 ---------------
#define BM 128
#define BN 128
#define BK 32
#define NK (KP / BK)     // 104
#define SSTR 40          // bf16 row stride (80 B): conflict-free ldmatrix

__global__ void __launch_bounds__(256, 2) gemm_mma(float* __restrict__ out) {
    __shared__ __nv_bfloat16 As[2][BM][SSTR];
    __shared__ __nv_bfloat16 Bs[2][BN][SSTR];

    const int tid = threadIdx.x, lane = tid & 31, wid = tid >> 5;
    const int wm = wid >> 2, wn = wid & 3;          // 2 x 4 warp grid
    const int b  = blockIdx.z;
    const int t0 = blockIdx.x * BM;
    const int n0 = blockIdx.y * BN;

    const __nv_bfloat16* Ab = g_A + ((size_t)b * MPAD + t0) * KP;
    const __nv_bfloat16* Bb = g_B + ((size_t)b * NPAD + n0) * KP;

    float acc[4][4][4];
    #pragma unroll
    for (int mi = 0; mi < 4; mi++)
        #pragma unroll
        for (int ni = 0; ni < 4; ni++)
            #pragma unroll
            for (int r = 0; r < 4; r++) acc[mi][ni][r] = 0.f;

    auto loadTile = [&](int kc, int st) {
        #pragma unroll
        for (int q = 0; q < 2; q++) {
            int idx = tid + q * 256;
            int row = idx >> 2, cc = (idx & 3) * 8;
            cp_async16((uint32_t)__cvta_generic_to_shared(&As[st][row][cc]),
                       Ab + (size_t)row * KP + kc * BK + cc);
        }
        #pragma unroll
        for (int q = 0; q < 2; q++) {
            int idx = tid + q * 256;
            int row = idx >> 2, cc = (idx & 3) * 8;
            cp_async16((uint32_t)__cvta_generic_to_shared(&Bs[st][row][cc]),
                       Bb + (size_t)row * KP + kc * BK + cc);
        }
        asm volatile("cp.async.commit_group;");
    };

    loadTile(0, 0);
    for (int kt = 0; kt < NK; kt++) {
        if (kt + 1 < NK) {
            loadTile(kt + 1, (kt + 1) & 1);
            asm volatile("cp.async.wait_group 1;" ::: "memory");
        } else {
            asm volatile("cp.async.wait_group 0;" ::: "memory");
        }
        __syncthreads();

        const int s = kt & 1;
        #pragma unroll
        for (int ks = 0; ks < 2; ks++) {
            uint32_t a[4][4], bf[4][2];
            #pragma unroll
            for (int mi = 0; mi < 4; mi++) {
                uint32_t ad = (uint32_t)__cvta_generic_to_shared(
                    &As[s][wm * 64 + mi * 16 + (lane & 15)][ks * 16 + (lane >> 4) * 8]);
                asm volatile("ldmatrix.sync.aligned.m8n8.x4.shared.b16 {%0,%1,%2,%3}, [%4];"
                    : "=r"(a[mi][0]), "=r"(a[mi][1]), "=r"(a[mi][2]), "=r"(a[mi][3]) : "r"(ad));
            }
            #pragma unroll
            for (int ni = 0; ni < 4; ni++) {
                uint32_t bd = (uint32_t)__cvta_generic_to_shared(
                    &Bs[s][wn * 32 + ni * 8 + (lane & 7)][ks * 16 + ((lane >> 3) & 1) * 8]);
                asm volatile("ldmatrix.sync.aligned.m8n8.x2.shared.b16 {%0,%1}, [%2];"
                    : "=r"(bf[ni][0]), "=r"(bf[ni][1]) : "r"(bd));
            }
            #pragma unroll
            for (int mi = 0; mi < 4; mi++)
                #pragma unroll
                for (int ni = 0; ni < 4; ni++)
                    asm volatile(
                        "mma.sync.aligned.m16n8k16.row.col.f32.bf16.bf16.f32 "
                        "{%0,%1,%2,%3}, {%4,%5,%6,%7}, {%8,%9}, {%0,%1,%2,%3};"
                        : "+f"(acc[mi][ni][0]), "+f"(acc[mi][ni][1]),
                          "+f"(acc[mi][ni][2]), "+f"(acc[mi][ni][3])
                        : "r"(a[mi][0]), "r"(a[mi][1]), "r"(a[mi][2]), "r"(a[mi][3]),
                          "r"(bf[ni][0]), "r"(bf[ni][1]));
        }
        __syncthreads();
    }

    // ---- epilogue: D[t, n] -> cropped output / mask_recon ----
    #pragma unroll
    for (int mi = 0; mi < 4; mi++) {
        #pragma unroll
        for (int rr = 0; rr < 2; rr++) {
            int t = t0 + wm * 64 + mi * 16 + (lane >> 2) + rr * 8;
            if (t >= TT) continue;
            int Ty = t / TDIM, Tx = t - Ty * TDIM;
            int cnt = ((Ty >= 1) + (Ty <= 31)) * ((Tx >= 1) + (Tx <= 31));
            float inv = 1.f / (float)cnt;
            #pragma unroll
            for (int ni = 0; ni < 4; ni++) {
                int n = n0 + wn * 32 + ni * 8 + (lane & 3) * 2;
                int c = n >> 6;
                if (c > CCH) continue;      // N padding
                int dy = (n >> 3) & 7, dx = n & 7;
                int py = Ty * 8 + dy - 4;
                if ((unsigned)py >= 256u) continue;
                int px = Tx * 8 + dx - 4;
                float sc = (c < CCH) ? 1.f : inv;
                float* dst = (c < CCH)
                    ? out + (((size_t)(b * CCH + c)) * IMG + py) * IMG
                    : out + OFF_MR + (((size_t)b) * IMG + py) * IMG;
                float v0 = acc[mi][ni][rr * 2]     * sc;
                float v1 = acc[mi][ni][rr * 2 + 1] * sc;
                if ((unsigned)px < 255u) {
                    float2 v = make_float2(v0, v1);
                    *(float2*)(dst + px) = v;
                } else {
                    if ((unsigned)px < 256u)       dst[px]     = v0;
                    if ((unsigned)(px + 1) < 256u) dst[px + 1] = v1;
                }
            }
        }
    }
}

// ---------------- K5: argmax ---------------------------------------------------
__global__ void argmax_kernel(const float* __restrict__ cosd) {
    int b  = blockIdx.y;
    int g  = blockIdx.x * 32 + threadIdx.x;
    int ty = threadIdx.y;
    const float* cb = cosd + (size_t)b * 1024 * 1024;
    float best = -3.4e38f;
    int   bi   = 1024;
    for (int n = ty; n < 1024; n += 8) {
        float v = cb[n * 1024 + g];
        if (v > best) { best = v; bi = n; }
    }
    __shared__ float sv[8][32];
    __shared__ int   si[8][32];
    sv[ty][threadIdx.x] = best;
    si[ty][threadIdx.x] = bi;
    __syncthreads();
    if (ty == 0) {
        #pragma unroll
        for (int r = 1; r < 8; r++) {
            float v = sv[r][threadIdx.x];
            int   i2 = si[r][threadIdx.x];
            if (v > best || (v == best && i2 < bi)) { best = v; bi = i2; }
        }
        g_ids[b * 1024 + g] = bi;
    }
}

// ---------------- K6: recon gather ---------------------------------------------
__global__ void recon_kernel(const float* __restrict__ aux, float* __restrict__ out) {
    int idx = blockIdx.x * blockDim.x + threadIdx.x;
    if (idx >= BATCH * 3 * IMG * IMG) return;
    int x = idx & 255;
    int y = (idx >> 8) & 255;
    int bc = idx >> 16;
    int b  = bc / 3;
    int py = y + 4, px = x + 4;
    int Ty = py >> 3, dy = py & 7;
    int Tx = px >> 3, dx = px & 7;
    const int*   ids = g_ids + b * 1024;
    const float* ab  = aux + (size_t)bc * IMG * IMG;
    float s = 0.f;
    #pragma unroll
    for (int qy = 0; qy < 2; qy++) {
        int gy = Ty - qy;
        if ((unsigned)gy >= GRID_) continue;
        int i = dy + 8 * qy;
        #pragma unroll
        for (int qx = 0; qx < 2; qx++) {
            int gx = Tx - qx;
            if ((unsigned)gx >= GRID_) continue;
            int j  = dx + 8 * qx;
            int id = ids[gy * 32 + gx];
            int u = (id >> 5) * 8 + i - 4; u = max(0, min(255, u));
            int v = (id & 31) * 8 + j - 4; v = max(0, min(255, v));
            s += ab[u * IMG + v];
        }
    }
    int cnty = (Ty >= 1) + (Ty <= 31);
    int cntx = (Tx >= 1) + (Tx <= 31);
    out[OFF_RC + idx] = s / (float)(cnty * cntx);
}

// ---------------- launch -------------------------------------------------------
extern "C" void kernel_launch(void* const* d_in, const int* in_sizes, int n_in,
                              void* d_out, int out_size) {
    const float* cosd = (const float*)d_in[0];
    const float* bimg = (const float*)d_in[1];
    const float* mask = (const float*)d_in[2];
    const float* aux  = (const float*)d_in[3];
    float* out = (float*)d_out;

    int na = BATCH * MPAD * KSEG;
    prep_A<<<(na + 255) / 256, 256>>>(cosd);

    int nb = BATCH * NPAD * KSEG;
    prep_B<<<(nb + 255) / 256, 256>>>(bimg, mask);

    int np = BATCH * (MPAD + NPAD) * 16;
    pad_K<<<(np + 255) / 256, 256>>>();

    argmax_kernel<<<dim3(32, BATCH), dim3(32, 8)>>>(cosd);

    gemm_mma<<<dim3(MPAD / BM, NPAD / BN, BATCH), 256>>>(out);

    int nr = BATCH * 3 * IMG * IMG;
    recon_kernel<<<(nr + 255) / 256, 256>>>(aux, out);
}